// round 1
// baseline (speedup 1.0000x reference)
#include <cuda_runtime.h>

// Problem constants
#define S_LEN   4096
#define NH      16
#define NB      16
#define NBH     (NB * NH)       // 256
#define DP      64              // p dim
#define DN      64              // n dim
#define TILE_T  64
#define NSEG    4               // split-K segments per (b,h)
#define LOGEPS  (-30.0f)        // w below exp(-30) ~ 9.4e-14 -> negligible

// Scratch (static device allocations are allowed)
__device__ float g_w[NBH * S_LEN];                 // 4 MB: w_t per (b,h)
__device__ int   g_tstart[NBH];                    // first useful t (tile-aligned)
__device__ float g_partial[NSEG * NBH * DP * DN];  // 16 MB split-K partials

// ---------------------------------------------------------------------------
// Kernel 1: per-(b,h) suffix sum of A over t, w_t = exp(S[t]), and dynamic
// truncation point t_start = first t with S[t] >= LOGEPS (tile-aligned).
// One block per (b,h), 256 threads, 16 contiguous t per thread.
// ---------------------------------------------------------------------------
__global__ void suffix_w_kernel(const float* __restrict__ A) {
    const int bh = blockIdx.x;
    const int b  = bh >> 4;
    const int h  = bh & 15;
    const int tid = threadIdx.x;          // 0..255
    const int t0  = tid * 16;

    const float* a = A + (size_t)b * S_LEN * NH + h;   // element t at a[t*NH]

    float vals[16];
    float lsum = 0.0f;
#pragma unroll
    for (int i = 0; i < 16; ++i) {
        vals[i] = a[(size_t)(t0 + i) * NH];
        lsum += vals[i];
    }

    // Inclusive suffix scan of per-thread sums (Hillis-Steele).
    __shared__ float ssum[256];
    ssum[tid] = lsum;
    __syncthreads();
#pragma unroll
    for (int d = 1; d < 256; d <<= 1) {
        float v = (tid + d < 256) ? ssum[tid + d] : 0.0f;
        __syncthreads();
        ssum[tid] += v;
        __syncthreads();
    }
    const float offset = ssum[tid] - lsum;   // sum over threads strictly after tid

    // Per-element suffix sums within this thread's 16 elements.
    float Sv[16];
    float run = offset;
#pragma unroll
    for (int i = 15; i >= 0; --i) {
        Sv[i] = run;          // S[t] = sum_{t' > t} a[t']
        run += vals[i];
    }

    __shared__ int smin;
    if (tid == 0) smin = S_LEN;
    __syncthreads();

    float* wout = g_w + (size_t)bh * S_LEN + t0;
    int mymin = S_LEN;
#pragma unroll
    for (int i = 0; i < 16; ++i) {
        wout[i] = expf(Sv[i]);
        if (Sv[i] >= LOGEPS && (t0 + i) < mymin) mymin = t0 + i;
    }
    if (mymin < S_LEN) atomicMin(&smin, mymin);
    __syncthreads();
    if (tid == 0) {
        int ts = smin;
        if (ts >= S_LEN) ts = S_LEN - TILE_T;   // safety (cannot happen: S[s-1]=0)
        g_tstart[bh] = (ts / TILE_T) * TILE_T;
    }
}

// ---------------------------------------------------------------------------
// Kernel 2: out_partial[seg][bh][p][n] = sum over assigned t-tiles of
//           w_t * X[t][p] * B[t][n]    (64x64 outer-product accumulation)
// grid = (NSEG, NBH), 256 threads, 4x4 register tile per thread.
// Deterministic split-K: tile `k` goes to segment k % NSEG.
// ---------------------------------------------------------------------------
__global__ void __launch_bounds__(256, 4)
outer_gemm_kernel(const float* __restrict__ X, const float* __restrict__ B) {
    const int seg = blockIdx.x;
    const int bh  = blockIdx.y;
    const int b   = bh >> 4;
    const int h   = bh & 15;
    const int tid = threadIdx.x;
    const int tx  = tid & 15;     // n-tile index
    const int ty  = tid >> 4;     // p-tile index

    __shared__ float xs[TILE_T][DP];  // 16 KB (w folded in)
    __shared__ float bs[TILE_T][DN];  // 16 KB

    float acc[4][4];
#pragma unroll
    for (int i = 0; i < 4; ++i)
#pragma unroll
        for (int j = 0; j < 4; ++j) acc[i][j] = 0.0f;

    const int   tstart = g_tstart[bh];
    const int   ntiles = (S_LEN - tstart) / TILE_T;
    const float* wrow  = g_w + (size_t)bh * S_LEN;

    const size_t strideT = (size_t)NH * DP;   // 1024 floats between t steps
    const float* Xb = X + ((size_t)b * S_LEN * NH + h) * DP;
    const float* Bb = B + ((size_t)b * S_LEN * NH + h) * DN;

    for (int tile = seg; tile < ntiles; tile += NSEG) {
        const int tb = tstart + tile * TILE_T;
        __syncthreads();   // protect smem reuse across iterations
#pragma unroll
        for (int k = 0; k < 4; ++k) {
            const int idx = tid + k * 256;   // 0..1023
            const int tt  = idx >> 4;        // t within tile
            const int q   = idx & 15;        // float4 slot within 64-float row
            const float w = wrow[tb + tt];   // L1-cached broadcast
            const float4 xv = *reinterpret_cast<const float4*>(
                Xb + (size_t)(tb + tt) * strideT + q * 4);
            float4 xw;
            xw.x = xv.x * w; xw.y = xv.y * w; xw.z = xv.z * w; xw.w = xv.w * w;
            *reinterpret_cast<float4*>(&xs[tt][q * 4]) = xw;
            const float4 bv = *reinterpret_cast<const float4*>(
                Bb + (size_t)(tb + tt) * strideT + q * 4);
            *reinterpret_cast<float4*>(&bs[tt][q * 4]) = bv;
        }
        __syncthreads();

#pragma unroll 16
        for (int tt = 0; tt < TILE_T; ++tt) {
            const float4 xv = *reinterpret_cast<const float4*>(&xs[tt][ty * 4]);
            const float4 bv = *reinterpret_cast<const float4*>(&bs[tt][tx * 4]);
            const float xr[4] = {xv.x, xv.y, xv.z, xv.w};
            const float br[4] = {bv.x, bv.y, bv.z, bv.w};
#pragma unroll
            for (int i = 0; i < 4; ++i)
#pragma unroll
                for (int j = 0; j < 4; ++j)
                    acc[i][j] = fmaf(xr[i], br[j], acc[i][j]);
        }
    }

    // Every (seg, bh) block writes its full partial tile (zeros if no tiles),
    // so g_partial never needs pre-zeroing and summation is deterministic.
    float* out = g_partial + ((size_t)seg * NBH + bh) * (DP * DN);
#pragma unroll
    for (int i = 0; i < 4; ++i) {
        const int p = ty * 4 + i;
        float4 v;
        v.x = acc[i][0]; v.y = acc[i][1]; v.z = acc[i][2]; v.w = acc[i][3];
        *reinterpret_cast<float4*>(out + p * DN + tx * 4) = v;
    }
}

// ---------------------------------------------------------------------------
// Kernel 3: reduce NSEG partials into d_out  (out layout: [b][h][p][n])
// ---------------------------------------------------------------------------
__global__ void reduce_kernel(float* __restrict__ out) {
    const int total = NBH * DP * DN;   // 1,048,576
    const int i = blockIdx.x * blockDim.x + threadIdx.x;
    if (i < total) {
        float s = g_partial[i];
#pragma unroll
        for (int k = 1; k < NSEG; ++k) s += g_partial[(size_t)k * total + i];
        out[i] = s;
    }
}

extern "C" void kernel_launch(void* const* d_in, const int* in_sizes, int n_in,
                              void* d_out, int out_size) {
    const float* X = (const float*)d_in[0];
    const float* A = (const float*)d_in[1];
    const float* B = (const float*)d_in[2];
    // d_in[3] (C) is unused by the reference's returned value.
    float* out = (float*)d_out;

    suffix_w_kernel<<<NBH, 256>>>(A);
    outer_gemm_kernel<<<dim3(NSEG, NBH), 256>>>(X, B);
    const int total = NBH * DP * DN;
    reduce_kernel<<<(total + 255) / 256, 256>>>(out);
}

// round 2
// speedup vs baseline: 1.8699x; 1.8699x over previous
#include <cuda_runtime.h>

// Problem constants
#define S_LEN   4096
#define NH      16
#define NB      16
#define NBH     (NB * NH)       // 256
#define DP      64              // p dim
#define DN      64              // n dim
#define TILE_T  64
#define NTILES  (S_LEN / TILE_T)  // 64
#define NSEG    2               // split-K segments per (b,h)
#define LOGEPS  (-12.0f)        // w below exp(-12)=6.1e-6 -> truncation rel-err ~6e-6

// Scratch (static device allocations are allowed)
__device__ float g_w[NBH * S_LEN];                 // 4 MB: w_t per (b,h), active region only
__device__ float g_tilesum[NBH * NTILES];          // 64 KB: per-tile sums of A
__device__ int   g_tstart[NBH];                    // first useful t (tile-aligned)
__device__ float g_partial[NSEG * NBH * DP * DN];  // 8 MB split-K partials

// ---------------------------------------------------------------------------
// Kernel A: fully-coalesced per-tile sums of A.
// A layout (b, s, h): element (b,t,h) at (b*S+t)*NH + h.
// Block handles (b, 512-t range): 8192 contiguous floats -> smem -> 8x16 tile sums.
// grid = 16 b * 8 ranges = 128 blocks, 256 threads.
// ---------------------------------------------------------------------------
__global__ void tilesum_kernel(const float* __restrict__ A) {
    const int b = blockIdx.x >> 3;
    const int r = blockIdx.x & 7;
    const int tid = threadIdx.x;

    __shared__ float sa[512 * NH];   // 32 KB

    const float* base = A + ((size_t)b * S_LEN + (size_t)r * 512) * NH;
#pragma unroll
    for (int i = 0; i < 8; ++i) {
        const int f = tid + i * 256;                 // float4 index, 0..2047
        *reinterpret_cast<float4*>(&sa[f * 4]) =
            *reinterpret_cast<const float4*>(base + (size_t)f * 4);
    }
    __syncthreads();

    if (tid < 128) {
        const int h    = tid & 15;
        const int tile = tid >> 4;                   // 0..7 (local)
        float s = 0.0f;
#pragma unroll 16
        for (int k = 0; k < TILE_T; ++k)
            s += sa[(tile * TILE_T + k) * NH + h];
        g_tilesum[((size_t)(b * NH + h)) * NTILES + (r * 8 + tile)] = s;
    }
}

// ---------------------------------------------------------------------------
// Kernel B: per-(b,h) tile-suffix scan -> exact active cutoff -> per-element w
// for the active window only. One block per bh, 256 threads (8 warps).
// Tile j is active iff SS_excl[j] = sum over tiles > j >= LOGEPS
// (w_max within tile j is exactly exp(SS_excl[j]) since a <= 0... a<=0 means
//  intra-tile suffix <= 0, so w <= exp(SS_excl[j]); bound is tight at tile end).
// ---------------------------------------------------------------------------
__global__ void cutoff_w_kernel(const float* __restrict__ A) {
    const int bh = blockIdx.x;
    const int b  = bh >> 4;
    const int h  = bh & 15;
    const int tid  = threadIdx.x;
    const int lane = tid & 31;
    const int wid  = tid >> 5;

    __shared__ float ssuf[NTILES];   // inclusive suffix of tile sums
    __shared__ int   sjmin;

    if (tid == 0) sjmin = NTILES - 1;   // last tile always active (SS_excl=0)
    if (tid < NTILES) ssuf[tid] = g_tilesum[(size_t)bh * NTILES + tid];
    __syncthreads();
    // Hillis-Steele inclusive suffix scan over 64 tiles
#pragma unroll
    for (int d = 1; d < NTILES; d <<= 1) {
        float v = 0.0f;
        if (tid < NTILES && tid + d < NTILES) v = ssuf[tid + d];
        __syncthreads();
        if (tid < NTILES) ssuf[tid] += v;
        __syncthreads();
    }
    // ssuf[j] is now inclusive suffix; SS_excl[j] = ssuf[j] - tilesum[j] = ssuf[j+1] (or 0)
    if (tid < NTILES) {
        const float ss_excl = (tid + 1 < NTILES) ? ssuf[tid + 1] : 0.0f;
        if (ss_excl >= LOGEPS) atomicMin(&sjmin, tid);
    }
    __syncthreads();
    const int jstart = sjmin;
    if (tid == 0) g_tstart[bh] = jstart * TILE_T;

    // Each warp computes w for one active tile (strided over warps).
    const float* a = A + ((size_t)b * S_LEN) * NH + h;
    float* wout = g_w + (size_t)bh * S_LEN;

    for (int j = jstart + wid; j < NTILES; j += 8) {
        const float ss_excl = (j + 1 < NTILES) ? ssuf[j + 1] : 0.0f;
        const int t0 = j * TILE_T;
        float v0 = a[(size_t)(t0 + lane) * NH];
        float v1 = a[(size_t)(t0 + 32 + lane) * NH];
        // inclusive suffix scans within each 32-half
        float s0 = v0, s1 = v1;
#pragma unroll
        for (int d = 1; d < 32; d <<= 1) {
            float u0 = __shfl_down_sync(0xffffffffu, s0, d);
            float u1 = __shfl_down_sync(0xffffffffu, s1, d);
            if (lane + d < 32) { s0 += u0; s1 += u1; }
        }
        const float tot_hi = __shfl_sync(0xffffffffu, s1, 0);  // sum of upper half
        // w_t = exp( suffix strictly after t within tile + SS_excl[j] )
        wout[t0 + lane]      = expf((s0 - v0) + tot_hi + ss_excl);
        wout[t0 + 32 + lane] = expf((s1 - v1) + ss_excl);
    }
}

// ---------------------------------------------------------------------------
// Kernel 2: out_partial[seg][bh][p][n] = sum over assigned t-tiles of
//           w_t * X[t][p] * B[t][n]    (64x64 outer-product accumulation)
// grid = (NSEG, NBH), 256 threads, 4x4 register tile per thread.
// Deterministic split-K: tile k -> segment k % NSEG.
// ---------------------------------------------------------------------------
__global__ void __launch_bounds__(256, 4)
outer_gemm_kernel(const float* __restrict__ X, const float* __restrict__ B) {
    const int seg = blockIdx.x;
    const int bh  = blockIdx.y;
    const int b   = bh >> 4;
    const int h   = bh & 15;
    const int tid = threadIdx.x;
    const int tx  = tid & 15;     // n-tile index
    const int ty  = tid >> 4;     // p-tile index

    __shared__ float xs[TILE_T][DP];  // 16 KB (w folded in)
    __shared__ float bs[TILE_T][DN];  // 16 KB

    float acc[4][4];
#pragma unroll
    for (int i = 0; i < 4; ++i)
#pragma unroll
        for (int j = 0; j < 4; ++j) acc[i][j] = 0.0f;

    const int   tstart = g_tstart[bh];
    const int   ntiles = (S_LEN - tstart) / TILE_T;
    const float* wrow  = g_w + (size_t)bh * S_LEN;

    const size_t strideT = (size_t)NH * DP;   // 1024 floats between t steps
    const float* Xb = X + ((size_t)b * S_LEN * NH + h) * DP;
    const float* Bb = B + ((size_t)b * S_LEN * NH + h) * DN;

    for (int tile = seg; tile < ntiles; tile += NSEG) {
        const int tb = tstart + tile * TILE_T;
        __syncthreads();   // protect smem reuse across iterations
#pragma unroll
        for (int k = 0; k < 4; ++k) {
            const int idx = tid + k * 256;   // 0..1023
            const int tt  = idx >> 4;        // t within tile
            const int q   = idx & 15;        // float4 slot within 64-float row
            const float w = wrow[tb + tt];   // broadcast within 16-thread group
            const float4 xv = *reinterpret_cast<const float4*>(
                Xb + (size_t)(tb + tt) * strideT + q * 4);
            float4 xw;
            xw.x = xv.x * w; xw.y = xv.y * w; xw.z = xv.z * w; xw.w = xv.w * w;
            *reinterpret_cast<float4*>(&xs[tt][q * 4]) = xw;
            const float4 bv = *reinterpret_cast<const float4*>(
                Bb + (size_t)(tb + tt) * strideT + q * 4);
            *reinterpret_cast<float4*>(&bs[tt][q * 4]) = bv;
        }
        __syncthreads();

#pragma unroll 16
        for (int tt = 0; tt < TILE_T; ++tt) {
            const float4 xv = *reinterpret_cast<const float4*>(&xs[tt][ty * 4]);
            const float4 bv = *reinterpret_cast<const float4*>(&bs[tt][tx * 4]);
            const float xr[4] = {xv.x, xv.y, xv.z, xv.w};
            const float br[4] = {bv.x, bv.y, bv.z, bv.w};
#pragma unroll
            for (int i = 0; i < 4; ++i)
#pragma unroll
                for (int j = 0; j < 4; ++j)
                    acc[i][j] = fmaf(xr[i], br[j], acc[i][j]);
        }
    }

    // Every (seg, bh) block writes its full partial tile (zeros if no tiles),
    // so g_partial never needs pre-zeroing and summation is deterministic.
    float* out = g_partial + ((size_t)seg * NBH + bh) * (DP * DN);
#pragma unroll
    for (int i = 0; i < 4; ++i) {
        const int p = ty * 4 + i;
        float4 v;
        v.x = acc[i][0]; v.y = acc[i][1]; v.z = acc[i][2]; v.w = acc[i][3];
        *reinterpret_cast<float4*>(out + p * DN + tx * 4) = v;
    }
}

// ---------------------------------------------------------------------------
// Kernel 3: reduce NSEG partials into d_out  (out layout: [b][h][p][n])
// ---------------------------------------------------------------------------
__global__ void reduce_kernel(float* __restrict__ out) {
    const int total = NBH * DP * DN;   // 1,048,576
    const int i = blockIdx.x * blockDim.x + threadIdx.x;
    if (i < total) {
        float s = g_partial[i];
#pragma unroll
        for (int k = 1; k < NSEG; ++k) s += g_partial[(size_t)k * total + i];
        out[i] = s;
    }
}

extern "C" void kernel_launch(void* const* d_in, const int* in_sizes, int n_in,
                              void* d_out, int out_size) {
    const float* X = (const float*)d_in[0];
    const float* A = (const float*)d_in[1];
    const float* B = (const float*)d_in[2];
    // d_in[3] (C) is unused by the reference's returned value.
    float* out = (float*)d_out;

    tilesum_kernel<<<NB * 8, 256>>>(A);
    cutoff_w_kernel<<<NBH, 256>>>(A);
    outer_gemm_kernel<<<dim3(NSEG, NBH), 256>>>(X, B);
    const int total = NBH * DP * DN;
    reduce_kernel<<<(total + 255) / 256, 256>>>(out);
}

// round 3
// speedup vs baseline: 2.7800x; 1.4867x over previous
#include <cuda_runtime.h>

// Problem constants
#define S_LEN   4096
#define NH      16
#define NB      16
#define NBH     (NB * NH)       // 256
#define DP      64              // p dim
#define DN      64              // n dim
#define TILE_T  64
#define NTILES  (S_LEN / TILE_T)  // 64
#define LOGEPS  (-9.0f)         // calibrated: rel_err ~= exp(LOGEPS)/~2 ≈ 1e-4 << 1e-3

// Scratch
__device__ float g_tilesum[NBH * NTILES];   // 64 KB: per-tile sums of A

// ---------------------------------------------------------------------------
// Kernel 1: fully-coalesced per-tile sums of A.
// A layout (b, s, h): element (b,t,h) at (b*S+t)*NH + h.
// Block handles (b, 512-t range): 8192 contiguous floats -> smem -> 8x16 sums.
// ---------------------------------------------------------------------------
__global__ void tilesum_kernel(const float* __restrict__ A) {
    const int b = blockIdx.x >> 3;
    const int r = blockIdx.x & 7;
    const int tid = threadIdx.x;

    __shared__ float sa[512 * NH];   // 32 KB

    const float* base = A + ((size_t)b * S_LEN + (size_t)r * 512) * NH;
#pragma unroll
    for (int i = 0; i < 8; ++i) {
        const int f = tid + i * 256;                 // float4 index, 0..2047
        *reinterpret_cast<float4*>(&sa[f * 4]) =
            *reinterpret_cast<const float4*>(base + (size_t)f * 4);
    }
    __syncthreads();

    if (tid < 128) {
        const int h    = tid & 15;
        const int tile = tid >> 4;                   // 0..7 (local)
        float s = 0.0f;
#pragma unroll 16
        for (int k = 0; k < TILE_T; ++k)
            s += sa[(tile * TILE_T + k) * NH + h];
        g_tilesum[((size_t)(b * NH + h)) * NTILES + (r * 8 + tile)] = s;
    }
}

// ---------------------------------------------------------------------------
// Kernel 2 (fused): per-(b,h) CTA.
//  Prologue: suffix-scan the 64 tile sums -> exact active-tile cutoff
//            (tile j active iff sum over tiles > j  >= LOGEPS; bound is tight
//             since a<=0), then compute w_t = exp(suffix after t) into smem
//            for the active window.
//  Mainloop: out[p][n] = sum over active t of w_t * X[t][p] * B[t][n]
//            64x64 outer-product accumulation, 4x4 register tile per thread.
//  Direct write to d_out: no split-K, no partials, no reduce.
// ---------------------------------------------------------------------------
__global__ void __launch_bounds__(256, 2)
fused_gemm_kernel(const float* __restrict__ X, const float* __restrict__ B,
                  const float* __restrict__ A, float* __restrict__ out) {
    const int bh = blockIdx.x;
    const int b  = bh >> 4;
    const int h  = bh & 15;
    const int tid  = threadIdx.x;
    const int lane = tid & 31;
    const int wid  = tid >> 5;
    const int tx   = tid & 15;    // n-tile index
    const int ty   = tid >> 4;    // p-tile index

    __shared__ float ssuf[NTILES];       // inclusive suffix of tile sums
    __shared__ float ws[S_LEN];          // 16 KB: w_t (only active region written)
    __shared__ float xs[TILE_T][DP];     // 16 KB (w folded in)
    __shared__ float bs[TILE_T][DN];     // 16 KB
    __shared__ int   sjmin;

    // ---- tile-level suffix scan + cutoff ----
    if (tid == 0) sjmin = NTILES - 1;    // last tile always active (excl suffix = 0)
    if (tid < NTILES) ssuf[tid] = g_tilesum[(size_t)bh * NTILES + tid];
    __syncthreads();
#pragma unroll
    for (int d = 1; d < NTILES; d <<= 1) {
        float v = 0.0f;
        if (tid < NTILES && tid + d < NTILES) v = ssuf[tid + d];
        __syncthreads();
        if (tid < NTILES) ssuf[tid] += v;
        __syncthreads();
    }
    if (tid < NTILES) {
        const float ss_excl = (tid + 1 < NTILES) ? ssuf[tid + 1] : 0.0f;
        if (ss_excl >= LOGEPS) atomicMin(&sjmin, tid);
    }
    __syncthreads();
    const int jstart = sjmin;

    // ---- per-element w for active tiles (warp-strided over tiles) ----
    const float* a = A + ((size_t)b * S_LEN) * NH + h;
    for (int j = jstart + wid; j < NTILES; j += 8) {
        const float ss_excl = (j + 1 < NTILES) ? ssuf[j + 1] : 0.0f;
        const int t0 = j * TILE_T;
        float v0 = a[(size_t)(t0 + lane) * NH];
        float v1 = a[(size_t)(t0 + 32 + lane) * NH];
        float s0 = v0, s1 = v1;     // inclusive suffix scans within each half
#pragma unroll
        for (int d = 1; d < 32; d <<= 1) {
            float u0 = __shfl_down_sync(0xffffffffu, s0, d);
            float u1 = __shfl_down_sync(0xffffffffu, s1, d);
            if (lane + d < 32) { s0 += u0; s1 += u1; }
        }
        const float tot_hi = __shfl_sync(0xffffffffu, s1, 0);  // sum of upper half
        ws[t0 + lane]      = expf((s0 - v0) + tot_hi + ss_excl);
        ws[t0 + 32 + lane] = expf((s1 - v1) + ss_excl);
    }
    __syncthreads();

    // ---- outer-product mainloop over active tiles ----
    float acc[4][4];
#pragma unroll
    for (int i = 0; i < 4; ++i)
#pragma unroll
        for (int j = 0; j < 4; ++j) acc[i][j] = 0.0f;

    const size_t strideT = (size_t)NH * DP;   // 1024 floats between t steps
    const float* Xb = X + ((size_t)b * S_LEN * NH + h) * DP;
    const float* Bb = B + ((size_t)b * S_LEN * NH + h) * DN;

    for (int tile = jstart; tile < NTILES; ++tile) {
        const int tb = tile * TILE_T;
#pragma unroll
        for (int k = 0; k < 4; ++k) {
            const int idx = tid + k * 256;   // 0..1023
            const int tt  = idx >> 4;        // t within tile
            const int q   = idx & 15;        // float4 slot within 64-float row
            const float w = ws[tb + tt];     // smem broadcast across 16 threads
            const float4 xv = *reinterpret_cast<const float4*>(
                Xb + (size_t)(tb + tt) * strideT + q * 4);
            float4 xw;
            xw.x = xv.x * w; xw.y = xv.y * w; xw.z = xv.z * w; xw.w = xv.w * w;
            *reinterpret_cast<float4*>(&xs[tt][q * 4]) = xw;
            const float4 bv = *reinterpret_cast<const float4*>(
                Bb + (size_t)(tb + tt) * strideT + q * 4);
            *reinterpret_cast<float4*>(&bs[tt][q * 4]) = bv;
        }
        __syncthreads();

#pragma unroll 16
        for (int tt = 0; tt < TILE_T; ++tt) {
            const float4 xv = *reinterpret_cast<const float4*>(&xs[tt][ty * 4]);
            const float4 bv = *reinterpret_cast<const float4*>(&bs[tt][tx * 4]);
            const float xr[4] = {xv.x, xv.y, xv.z, xv.w};
            const float br[4] = {bv.x, bv.y, bv.z, bv.w};
#pragma unroll
            for (int i = 0; i < 4; ++i)
#pragma unroll
                for (int j = 0; j < 4; ++j)
                    acc[i][j] = fmaf(xr[i], br[j], acc[i][j]);
        }
        __syncthreads();   // protect smem reuse in the next iteration
    }

    // ---- direct output write: out[b][h][p][n] ----
    float* o = out + (size_t)bh * (DP * DN);
#pragma unroll
    for (int i = 0; i < 4; ++i) {
        const int p = ty * 4 + i;
        float4 v;
        v.x = acc[i][0]; v.y = acc[i][1]; v.z = acc[i][2]; v.w = acc[i][3];
        *reinterpret_cast<float4*>(o + p * DN + tx * 4) = v;
    }
}

extern "C" void kernel_launch(void* const* d_in, const int* in_sizes, int n_in,
                              void* d_out, int out_size) {
    const float* X = (const float*)d_in[0];
    const float* A = (const float*)d_in[1];
    const float* B = (const float*)d_in[2];
    // d_in[3] (C) is unused by the reference's returned value.
    float* out = (float*)d_out;

    tilesum_kernel<<<NB * 8, 256>>>(A);
    fused_gemm_kernel<<<NBH, 256>>>(X, B, A, out);
}